// round 2
// baseline (speedup 1.0000x reference)
#include <cuda_runtime.h>
#include <cuda_bf16.h>

// MaxPool3d kernel=2 stride=2 over [B=2, C=32, D=128, H=128, W=128] fp32.
// Output [2, 32, 64, 64, 64].
//
// Layout facts:
//   in  index = bc*128^3 + d*128^2 + h*128 + w      (bc = b*32 + c, 64 planes)
//   out index = bc*64^3  + d*64^2  + h*64  + w
//
// Each thread produces 4 consecutive outputs along W:
//   reads 8 consecutive inputs (2x float4) from each of 4 rows
//   (d0/d1 x h0/h1), maxes pairwise, writes one float4.
// 8 independent float4 loads per thread -> high MLP, fully coalesced.

#define OUT_W 64
#define OUT_H 64
#define OUT_D 64
#define IN_W 128
#define IN_HW (128 * 128)
#define IN_DHW (128 * 128 * 128)
#define OUT_HW (64 * 64)
#define OUT_DHW (64 * 64 * 64)

__global__ __launch_bounds__(256) void maxpool3d_k2s2_kernel(
    const float* __restrict__ in, float* __restrict__ out, int n_quads)
{
    int t = blockIdx.x * blockDim.x + threadIdx.x;
    if (t >= n_quads) return;

    // Each thread: 4 outputs along W. 16 quads per output row (64/4).
    int w4 = t & 15;                 // quad index along out W
    int h  = (t >> 4) & 63;          // out h
    int d  = (t >> 10) & 63;         // out d
    int bc = t >> 16;                // plane (b*C + c), 0..63

    int id = d << 1;
    int ih = h << 1;
    int iw = w4 << 3;                // 8 input floats start

    const float4* r00 = (const float4*)(in + (size_t)bc * IN_DHW + (size_t)id * IN_HW       + (size_t)ih * IN_W       + iw);
    const float4* r01 = (const float4*)(in + (size_t)bc * IN_DHW + (size_t)id * IN_HW       + (size_t)(ih + 1) * IN_W + iw);
    const float4* r10 = (const float4*)(in + (size_t)bc * IN_DHW + (size_t)(id + 1) * IN_HW + (size_t)ih * IN_W       + iw);
    const float4* r11 = (const float4*)(in + (size_t)bc * IN_DHW + (size_t)(id + 1) * IN_HW + (size_t)(ih + 1) * IN_W + iw);

    // Front-batch all 8 loads (MLP=8).
    float4 a0 = r00[0], a1 = r00[1];
    float4 b0 = r01[0], b1 = r01[1];
    float4 c0 = r10[0], c1 = r10[1];
    float4 e0 = r11[0], e1 = r11[1];

    // Reduce across the 4 rows first.
    float4 m0, m1;
    m0.x = fmaxf(fmaxf(a0.x, b0.x), fmaxf(c0.x, e0.x));
    m0.y = fmaxf(fmaxf(a0.y, b0.y), fmaxf(c0.y, e0.y));
    m0.z = fmaxf(fmaxf(a0.z, b0.z), fmaxf(c0.z, e0.z));
    m0.w = fmaxf(fmaxf(a0.w, b0.w), fmaxf(c0.w, e0.w));
    m1.x = fmaxf(fmaxf(a1.x, b1.x), fmaxf(c1.x, e1.x));
    m1.y = fmaxf(fmaxf(a1.y, b1.y), fmaxf(c1.y, e1.y));
    m1.z = fmaxf(fmaxf(a1.z, b1.z), fmaxf(c1.z, e1.z));
    m1.w = fmaxf(fmaxf(a1.w, b1.w), fmaxf(c1.w, e1.w));

    // Pairwise max along W: (m0.x,m0.y)->o.x, (m0.z,m0.w)->o.y, etc.
    float4 o;
    o.x = fmaxf(m0.x, m0.y);
    o.y = fmaxf(m0.z, m0.w);
    o.z = fmaxf(m1.x, m1.y);
    o.w = fmaxf(m1.z, m1.w);

    float4* op = (float4*)(out + (size_t)bc * OUT_DHW + (size_t)d * OUT_HW + (size_t)h * OUT_W + (w4 << 2));
    op[0] = o;
}

extern "C" void kernel_launch(void* const* d_in, const int* in_sizes, int n_in,
                              void* d_out, int out_size)
{
    const float* in = (const float*)d_in[0];
    float* out = (float*)d_out;

    // out_size = 2*32*64*64*64 = 16,777,216; each thread writes 4 -> 4,194,304 threads
    int n_quads = out_size / 4;
    int threads = 256;
    int blocks = (n_quads + threads - 1) / threads;
    maxpool3d_k2s2_kernel<<<blocks, threads>>>(in, out, n_quads);
}